// round 3
// baseline (speedup 1.0000x reference)
#include <cuda_runtime.h>
#include <math.h>

// Router gate: probs = softmax(h @ W^T * scale + bias), top-8 (weights, indices).
// T=16384 tokens, D=2048, E=64 experts. fp32, f32x2-packed FFMA,
// blocked (DK=16) hierarchical accumulation for cuBLAS-class rounding error.

#define TDIM 2048
#define NEXP 64
#define TOPK 8
#define TM   128          // tokens per CTA
#define DK   16           // k-chunk
#define NTH  256          // threads per CTA (32 token-threads x 8 expert-threads)
#define HP   20           // h smem row stride (floats, padded)
#define WP   66           // w smem row stride (experts, pad 2, 8B-aligned pairs)
#define WOFF (TM * HP)                  // 2560 floats
#define SMEM_FLOATS (TM * WP)           // 8448 floats (>= WOFF + DK*WP = 3616)

typedef unsigned long long u64t;

__device__ __forceinline__ u64t dup_f32(float x) {
    u64t r;
    asm("mov.b64 %0, {%1, %1};" : "=l"(r) : "r"(__float_as_uint(x)));
    return r;
}
__device__ __forceinline__ void fma_f32x2(u64t& c, u64t a, u64t b) {
    asm("fma.rn.f32x2 %0, %1, %2, %0;" : "+l"(c) : "l"(a), "l"(b));
}
__device__ __forceinline__ u64t add_f32x2(u64t a, u64t b) {
    u64t r;
    asm("add.rn.f32x2 %0, %1, %2;" : "=l"(r) : "l"(a), "l"(b));
    return r;
}
__device__ __forceinline__ void unpack_f32x2(u64t v, float& lo, float& hi) {
    unsigned int l, h;
    asm("mov.b64 {%0, %1}, %2;" : "=r"(l), "=r"(h) : "l"(v));
    lo = __uint_as_float(l);
    hi = __uint_as_float(h);
}

// top-8 insertion, jax.lax.top_k semantics: descending, ties -> smaller index
// first. Strict '>' on entry and bubble-up gives exactly that.
#define TOPK_INSERT(p, e)                                              \
    do {                                                               \
        if ((p) > tv[7]) {                                             \
            tv[7] = (p); tix[7] = (e);                                 \
            _Pragma("unroll")                                          \
            for (int _r = 7; _r > 0; _r--) {                           \
                if (tv[_r] > tv[_r - 1]) {                             \
                    float _tv = tv[_r]; tv[_r] = tv[_r-1]; tv[_r-1] = _tv; \
                    int   _ti = tix[_r]; tix[_r] = tix[_r-1]; tix[_r-1] = _ti; \
                }                                                      \
            }                                                          \
        }                                                              \
    } while (0)

__global__ __launch_bounds__(NTH)
void router_gate_kernel(const float* __restrict__ hs,
                        const float* __restrict__ rw,
                        const float* __restrict__ cs,
                        const float* __restrict__ cb,
                        float* __restrict__ out,
                        int T)
{
    __shared__ __align__(16) float sm[SMEM_FLOATS];
    __shared__ float s_cs[NEXP], s_cb[NEXP];

    const int tid = threadIdx.x;
    const int tx  = tid & 7;    // expert pairs (2tx+16j, 2tx+16j+1), j=0..3
    const int ty  = tid >> 3;   // tokens ty + 32*i, i=0..3
    const int t0  = blockIdx.x * TM;
    const float* hblk = hs + (long long)t0 * TDIM;

    if (tid < NEXP) { s_cs[tid] = cs[tid]; s_cb[tid] = cb[tid]; }

    // totals + per-chunk accumulators (packed f32x2: expert pair per reg-pair)
    u64t acc[4][4], chk[4][4];
    #pragma unroll
    for (int i = 0; i < 4; i++)
        #pragma unroll
        for (int j = 0; j < 4; j++) { acc[i][j] = 0ull; chk[i][j] = 0ull; }

    float4 ph[2];   // h chunk prefetch: 128x16 floats = 2 float4/thread
    float4 pw;      // w chunk prefetch:  64x16 floats = 1 float4/thread

    const int hrow = tid >> 2;        // 0..63
    const int hk4  = (tid & 3) * 4;   // 0,4,8,12
    const int we   = tid >> 2;        // expert 0..63
    const int wkv  = tid & 3;         // k-quad 0..3

    auto loadg = [&](int kc) {
        #pragma unroll
        for (int p = 0; p < 2; p++) {
            int r = hrow + 64 * p;
            ph[p] = *reinterpret_cast<const float4*>(hblk + r * TDIM + kc + hk4);
        }
        pw = *reinterpret_cast<const float4*>(rw + we * TDIM + kc + wkv * 4);
    };

    auto sts = [&]() {
        #pragma unroll
        for (int p = 0; p < 2; p++) {
            int r = hrow + 64 * p;
            *reinterpret_cast<float4*>(&sm[r * HP + hk4]) = ph[p];
        }
        // w transposed: w_s[k][e] so expert pairs are contiguous (LDS.64)
        sm[WOFF + (wkv * 4 + 0) * WP + we] = pw.x;
        sm[WOFF + (wkv * 4 + 1) * WP + we] = pw.y;
        sm[WOFF + (wkv * 4 + 2) * WP + we] = pw.z;
        sm[WOFF + (wkv * 4 + 3) * WP + we] = pw.w;
    };

    auto compute = [&]() {
        #pragma unroll
        for (int k = 0; k < DK; k++) {
            u64t b2[4];
            #pragma unroll
            for (int j = 0; j < 4; j++)
                b2[j] = *reinterpret_cast<const u64t*>(
                            &sm[WOFF + k * WP + 2 * tx + 16 * j]);
            #pragma unroll
            for (int i = 0; i < 4; i++) {
                u64t a2 = dup_f32(sm[(ty + 32 * i) * HP + k]);
                #pragma unroll
                for (int j = 0; j < 4; j++)
                    fma_f32x2(chk[i][j], a2, b2[j]);
            }
        }
        // merge chunk into totals (blocked summation -> ~2e-7 total error)
        #pragma unroll
        for (int i = 0; i < 4; i++)
            #pragma unroll
            for (int j = 0; j < 4; j++) {
                acc[i][j] = add_f32x2(acc[i][j], chk[i][j]);
                chk[i][j] = 0ull;
            }
    };

    const int NC = TDIM / DK;   // 128 chunks
    loadg(0);
    for (int c = 0; c < NC; c++) {
        sts();
        __syncthreads();
        if (c + 1 < NC) loadg((c + 1) * DK);   // overlap next DRAM with compute
        compute();
        __syncthreads();
    }

    // ---- epilogue: calibrate, stage logits to smem (reuses tile space) ----
    #pragma unroll
    for (int i = 0; i < 4; i++) {
        int t = ty + 32 * i;
        #pragma unroll
        for (int j = 0; j < 4; j++) {
            int e0 = 2 * tx + 16 * j;
            float lo, hi;
            unpack_f32x2(acc[i][j], lo, hi);
            float l0 = lo * s_cs[e0]     + s_cb[e0];
            float l1 = hi * s_cs[e0 + 1] + s_cb[e0 + 1];
            *reinterpret_cast<float2*>(&sm[t * WP + e0]) = make_float2(l0, l1);
        }
    }
    __syncthreads();

    // ---- per-token softmax + top-8: one thread per token (tid < 128) ----
    if (tid < TM) {
        const int t  = tid;
        const int gt = t0 + t;
        float* row = &sm[t * WP];

        float m = row[0];
        #pragma unroll
        for (int e = 1; e < NEXP; e++) m = fmaxf(m, row[e]);

        float s = 0.f;
        #pragma unroll
        for (int e = 0; e < NEXP; e++) {
            float p = expf(row[e] - m);
            s += p;
            row[e] = p;
        }

        float tv[TOPK];
        int   tix[TOPK];
        #pragma unroll
        for (int r = 0; r < TOPK; r++) { tv[r] = -1.f; tix[r] = 0; }

        float* oprobs = out;                                 // [T,64]
        float* ow     = out + (long long)T * NEXP;           // [T,8]
        float* oi     = ow  + (long long)T * TOPK;           // [T,8] (idx as f32)

        #pragma unroll
        for (int e = 0; e < NEXP; e += 4) {
            // IEEE division (matches reference's exp/sum elementwise divide)
            float p0 = row[e]     / s;
            float p1 = row[e + 1] / s;
            float p2 = row[e + 2] / s;
            float p3 = row[e + 3] / s;
            *reinterpret_cast<float4*>(&oprobs[(long long)gt * NEXP + e]) =
                make_float4(p0, p1, p2, p3);
            TOPK_INSERT(p0, e);
            TOPK_INSERT(p1, e + 1);
            TOPK_INSERT(p2, e + 2);
            TOPK_INSERT(p3, e + 3);
        }

        #pragma unroll
        for (int r = 0; r < TOPK; r++) {
            ow[(long long)gt * TOPK + r] = tv[r];
            oi[(long long)gt * TOPK + r] = (float)tix[r];
        }
    }
}

extern "C" void kernel_launch(void* const* d_in, const int* in_sizes, int n_in,
                              void* d_out, int out_size)
{
    (void)n_in; (void)out_size;
    const float* hs = (const float*)d_in[0];   // hidden_states [4,4096,2048]
    const float* rw = (const float*)d_in[1];   // router_weight [64,2048]
    const float* cs = (const float*)d_in[2];   // cal_scale [64]
    const float* cb = (const float*)d_in[3];   // cal_bias  [64]
    int T = in_sizes[0] / TDIM;                // 16384
    int grid = T / TM;                         // 128 CTAs
    router_gate_kernel<<<grid, NTH>>>(hs, rw, cs, cb, (float*)d_out, T);
}